// round 3
// baseline (speedup 1.0000x reference)
#include <cuda_runtime.h>
#include <math.h>

#define BATCH 8
#define SEQ 1213
#define NHEAD 12
#define DHEAD 64
#define HIDDIM 768
#define INTERDIM 3072
#define MROWS (BATCH*SEQ)      // 9704
#define NLEAD 12

// ---------------- scratch (static device globals; no allocation allowed) ----
__device__ float g_q[(size_t)BATCH*NHEAD*SEQ*DHEAD];
__device__ float g_k[(size_t)BATCH*NHEAD*SEQ*DHEAD];
__device__ float g_v[(size_t)BATCH*NHEAD*SEQ*DHEAD];
__device__ float g_ctx[(size_t)MROWS*HIDDIM];
__device__ float g_t1[(size_t)MROWS*HIDDIM];
__device__ float g_attn[(size_t)MROWS*HIDDIM];
__device__ float g_inter[(size_t)MROWS*INTERDIM];
__device__ float g_t2[(size_t)MROWS*HIDDIM];

// ---------------- SGEMM: C[M,N] = A[M,K] @ W[K,N] (+epilogue) ----------------
// BM=128, BN=64, BK=16, 256 threads, 8x4 register tile per thread.
#define BM 128
#define BN 64
#define BK 16
#define APAD 4

enum { MODE_QKV = 0, MODE_RES = 1, MODE_GELU = 2 };

template<int MODE>
__global__ __launch_bounds__(256)
void sgemm_kernel(const float* __restrict__ A, const float* __restrict__ W,
                  const float* __restrict__ bias, const float* __restrict__ Rsd,
                  float* __restrict__ out, int K, int N)
{
    __shared__ float As[BK][BM + APAD];
    __shared__ float Bs[BK][BN];

    const int tid = threadIdx.x;
    const int tx = tid & 15;        // 0..15 -> N
    const int ty = tid >> 4;        // 0..15 -> M
    const int m0 = blockIdx.x * BM;
    const int n0 = blockIdx.y * BN;

    float acc[8][4];
#pragma unroll
    for (int i = 0; i < 8; i++)
#pragma unroll
        for (int j = 0; j < 4; j++) acc[i][j] = 0.f;

    for (int k0 = 0; k0 < K; k0 += BK) {
        // load A tile (transposed into As[k][m]); K always multiple of 16
#pragma unroll
        for (int c = 0; c < 2; c++) {
            int s = tid + c * 256;          // 512 float4 slots
            int m = s >> 2;
            int kq = (s & 3) * 4;
            float4 v = make_float4(0.f, 0.f, 0.f, 0.f);
            if (m0 + m < MROWS)
                v = *reinterpret_cast<const float4*>(A + (size_t)(m0 + m) * K + k0 + kq);
            As[kq + 0][m] = v.x;
            As[kq + 1][m] = v.y;
            As[kq + 2][m] = v.z;
            As[kq + 3][m] = v.w;
        }
        // load B tile (row-contiguous)
        {
            int k = tid >> 4;
            int nq = (tid & 15) * 4;
            *reinterpret_cast<float4*>(&Bs[k][nq]) =
                *reinterpret_cast<const float4*>(W + (size_t)(k0 + k) * N + n0 + nq);
        }
        __syncthreads();

#pragma unroll
        for (int k = 0; k < BK; k++) {
            float a[8], b[4];
            *reinterpret_cast<float4*>(a)     = *reinterpret_cast<float4*>(&As[k][ty * 8]);
            *reinterpret_cast<float4*>(a + 4) = *reinterpret_cast<float4*>(&As[k][ty * 8 + 4]);
            *reinterpret_cast<float4*>(b)     = *reinterpret_cast<float4*>(&Bs[k][tx * 4]);
#pragma unroll
            for (int i = 0; i < 8; i++)
#pragma unroll
                for (int j = 0; j < 4; j++)
                    acc[i][j] += a[i] * b[j];
        }
        __syncthreads();
    }

    const float4 bias4 = *reinterpret_cast<const float4*>(bias + n0 + tx * 4);

    if (MODE == MODE_QKV) {
        // store into [B, H, S, DH]; BN == DHEAD so tile is one head
        const int h = n0 / DHEAD;
        const int d = tx * 4;
#pragma unroll
        for (int i = 0; i < 8; i++) {
            int m = m0 + ty * 8 + i;
            if (m < MROWS) {
                int bb = m / SEQ, srow = m % SEQ;
                float4 o;
                o.x = acc[i][0] + bias4.x;
                o.y = acc[i][1] + bias4.y;
                o.z = acc[i][2] + bias4.z;
                o.w = acc[i][3] + bias4.w;
                *reinterpret_cast<float4*>(
                    out + (((size_t)bb * NHEAD + h) * SEQ + srow) * DHEAD + d) = o;
            }
        }
    } else if (MODE == MODE_RES) {
#pragma unroll
        for (int i = 0; i < 8; i++) {
            int m = m0 + ty * 8 + i;
            if (m < MROWS) {
                float4 r = *reinterpret_cast<const float4*>(Rsd + (size_t)m * N + n0 + tx * 4);
                float4 o;
                o.x = acc[i][0] + bias4.x + r.x;
                o.y = acc[i][1] + bias4.y + r.y;
                o.z = acc[i][2] + bias4.z + r.z;
                o.w = acc[i][3] + bias4.w + r.w;
                *reinterpret_cast<float4*>(out + (size_t)m * N + n0 + tx * 4) = o;
            }
        }
    } else { // MODE_GELU (exact erf gelu)
#pragma unroll
        for (int i = 0; i < 8; i++) {
            int m = m0 + ty * 8 + i;
            if (m < MROWS) {
                float x0 = acc[i][0] + bias4.x;
                float x1 = acc[i][1] + bias4.y;
                float x2 = acc[i][2] + bias4.z;
                float x3 = acc[i][3] + bias4.w;
                float4 o;
                o.x = 0.5f * x0 * (1.f + erff(x0 * 0.70710678118654752f));
                o.y = 0.5f * x1 * (1.f + erff(x1 * 0.70710678118654752f));
                o.z = 0.5f * x2 * (1.f + erff(x2 * 0.70710678118654752f));
                o.w = 0.5f * x3 * (1.f + erff(x3 * 0.70710678118654752f));
                *reinterpret_cast<float4*>(out + (size_t)m * N + n0 + tx * 4) = o;
            }
        }
    }
}

// ---------------- Flash attention (fp32, 64x64 tiles, online softmax) -------
#define QT 64
#define KT 64
#define FPAD 68
#define FLASH_SMEM ((4 * 64 * FPAD + 3 * 64) * 4)   // 70400 bytes

__global__ __launch_bounds__(256)
void flash_attn_kernel(const float* __restrict__ Q, const float* __restrict__ Kg,
                       const float* __restrict__ Vg, const float* __restrict__ amask,
                       float* __restrict__ ctx)
{
    extern __shared__ float sm[];
    float* sQt = sm;                       // [d][q] 64 x FPAD
    float* sKt = sQt + 64 * FPAD;          // [d][k]
    float* sV  = sKt + 64 * FPAD;          // [k][d]
    float* sPt = sV  + 64 * FPAD;          // [k][q]
    float* sM  = sPt + 64 * FPAD;          // [64]
    float* sL  = sM + 64;
    float* sF  = sL + 64;

    const int qt = blockIdx.x;
    const int h  = blockIdx.y;
    const int b  = blockIdx.z;
    const int tid = threadIdx.x;
    const int tx = tid & 15;               // -> k (scores) / d (PV)
    const int ty = tid >> 4;               // -> q
    const size_t base = ((size_t)b * NHEAD + h) * SEQ * DHEAD;
    const int q0 = qt * QT;

    // load Q tile, transposed to [d][q]
    for (int s = tid; s < 64 * 16; s += 256) {
        int q = s >> 4;
        int dq = (s & 15) * 4;
        float4 v = make_float4(0.f, 0.f, 0.f, 0.f);
        if (q0 + q < SEQ)
            v = *reinterpret_cast<const float4*>(Q + base + (size_t)(q0 + q) * DHEAD + dq);
        sQt[(dq + 0) * FPAD + q] = v.x;
        sQt[(dq + 1) * FPAD + q] = v.y;
        sQt[(dq + 2) * FPAD + q] = v.z;
        sQt[(dq + 3) * FPAD + q] = v.w;
    }
    if (tid < 64) { sM[tid] = -1e30f; sL[tid] = 0.f; }

    float acc[4][4];
#pragma unroll
    for (int i = 0; i < 4; i++)
#pragma unroll
        for (int j = 0; j < 4; j++) acc[i][j] = 0.f;

    __syncthreads();

    const int nkt = (SEQ + KT - 1) / KT;   // 19
    for (int kt = 0; kt < nkt; kt++) {
        const int k0 = kt * KT;
        // load K (transposed) and V tiles
        for (int s = tid; s < 64 * 16; s += 256) {
            int k = s >> 4;
            int dq = (s & 15) * 4;
            float4 kv = make_float4(0.f, 0.f, 0.f, 0.f);
            float4 vv = make_float4(0.f, 0.f, 0.f, 0.f);
            if (k0 + k < SEQ) {
                kv = *reinterpret_cast<const float4*>(Kg + base + (size_t)(k0 + k) * DHEAD + dq);
                vv = *reinterpret_cast<const float4*>(Vg + base + (size_t)(k0 + k) * DHEAD + dq);
            }
            sKt[(dq + 0) * FPAD + k] = kv.x;
            sKt[(dq + 1) * FPAD + k] = kv.y;
            sKt[(dq + 2) * FPAD + k] = kv.z;
            sKt[(dq + 3) * FPAD + k] = kv.w;
            *reinterpret_cast<float4*>(&sV[k * FPAD + dq]) = vv;
        }
        __syncthreads();

        // scores S = Q @ K^T (4x4 micro-tile per thread)
        float sc[4][4];
#pragma unroll
        for (int i = 0; i < 4; i++)
#pragma unroll
            for (int j = 0; j < 4; j++) sc[i][j] = 0.f;
#pragma unroll 8
        for (int d = 0; d < 64; d++) {
            float q4[4], k4[4];
            *reinterpret_cast<float4*>(q4) = *reinterpret_cast<float4*>(&sQt[d * FPAD + ty * 4]);
            *reinterpret_cast<float4*>(k4) = *reinterpret_cast<float4*>(&sKt[d * FPAD + tx * 4]);
#pragma unroll
            for (int i = 0; i < 4; i++)
#pragma unroll
                for (int j = 0; j < 4; j++)
                    sc[i][j] += q4[i] * k4[j];
        }
        // mask + write (transposed) to sPt[k][q]
#pragma unroll
        for (int j = 0; j < 4; j++) {
            int kg = k0 + tx * 4 + j;
            float am = (kg < SEQ) ? amask[(size_t)b * SEQ + kg] : 0.f;
#pragma unroll
            for (int i = 0; i < 4; i++) {
                int qg = q0 + ty * 4 + i;
                float val;
                if (kg >= SEQ) {
                    val = -1e30f;
                } else {
                    val = sc[i][j] * 0.125f + am;
                    if (qg == 0) {
                        if (kg >= 1 && kg < 1 + NLEAD) val += -99999.f;
                    } else if (qg >= 1 && qg <= NLEAD) {
                        int start = NLEAD + 1 + 100 * (qg - 1);
                        bool inb = (kg >= start) && (kg < start + 100);
                        if (!inb) val += -99999.f;
                    }
                }
                sPt[(tx * 4 + j) * FPAD + (ty * 4 + i)] = val;
            }
        }
        __syncthreads();

        // per-row online softmax update (threads 0..63, one per q row)
        if (tid < 64) {
            int q = tid;
            float mold = sM[q];
            float mt = -1e30f;
            for (int k = 0; k < KT; k++) mt = fmaxf(mt, sPt[k * FPAD + q]);
            float mnew = fmaxf(mold, mt);
            float fac = __expf(mold - mnew);
            float ls = 0.f;
            for (int k = 0; k < KT; k++) {
                float p = __expf(sPt[k * FPAD + q] - mnew);
                sPt[k * FPAD + q] = p;
                ls += p;
            }
            sL[q] = sL[q] * fac + ls;
            sM[q] = mnew;
            sF[q] = fac;
        }
        __syncthreads();

        // rescale accumulators, then acc += P @ V
        float f4[4];
#pragma unroll
        for (int i = 0; i < 4; i++) f4[i] = sF[ty * 4 + i];
#pragma unroll
        for (int i = 0; i < 4; i++)
#pragma unroll
            for (int j = 0; j < 4; j++) acc[i][j] *= f4[i];

#pragma unroll 8
        for (int k = 0; k < KT; k++) {
            float p4[4], v4[4];
            *reinterpret_cast<float4*>(p4) = *reinterpret_cast<float4*>(&sPt[k * FPAD + ty * 4]);
            *reinterpret_cast<float4*>(v4) = *reinterpret_cast<float4*>(&sV[k * FPAD + tx * 4]);
#pragma unroll
            for (int i = 0; i < 4; i++)
#pragma unroll
                for (int j = 0; j < 4; j++)
                    acc[i][j] += p4[i] * v4[j];
        }
        __syncthreads();
    }

    // write ctx in [B, S, HID]
#pragma unroll
    for (int i = 0; i < 4; i++) {
        int qg = q0 + ty * 4 + i;
        if (qg < SEQ) {
            float invl = 1.f / sL[ty * 4 + i];
            float4 o;
            o.x = acc[i][0] * invl;
            o.y = acc[i][1] * invl;
            o.z = acc[i][2] * invl;
            o.w = acc[i][3] * invl;
            *reinterpret_cast<float4*>(
                ctx + ((size_t)b * SEQ + qg) * HIDDIM + h * DHEAD + tx * 4) = o;
        }
    }
}

// ---------------- LayerNorm (one block per row, HID=768, 256 threads) -------
__global__ __launch_bounds__(256)
void layernorm_kernel(const float* __restrict__ x, const float* __restrict__ g,
                      const float* __restrict__ bb, float* __restrict__ y)
{
    __shared__ float red[8];
    __shared__ float sMean, sRstd;
    const int row = blockIdx.x;
    const int tid = threadIdx.x;
    const float* xr = x + (size_t)row * HIDDIM;

    float v[3];
    float sum = 0.f;
#pragma unroll
    for (int i = 0; i < 3; i++) { v[i] = xr[tid + i * 256]; sum += v[i]; }

#pragma unroll
    for (int o = 16; o > 0; o >>= 1) sum += __shfl_down_sync(0xffffffffu, sum, o);
    if ((tid & 31) == 0) red[tid >> 5] = sum;
    __syncthreads();
    if (tid < 32) {
        float t = (tid < 8) ? red[tid] : 0.f;
#pragma unroll
        for (int o = 4; o > 0; o >>= 1) t += __shfl_down_sync(0xffffffffu, t, o);
        if (tid == 0) sMean = t * (1.f / HIDDIM);
    }
    __syncthreads();
    const float mean = sMean;

    float sq = 0.f;
#pragma unroll
    for (int i = 0; i < 3; i++) { float d = v[i] - mean; sq += d * d; }
#pragma unroll
    for (int o = 16; o > 0; o >>= 1) sq += __shfl_down_sync(0xffffffffu, sq, o);
    __syncthreads();   // red[] reuse safety
    if ((tid & 31) == 0) red[tid >> 5] = sq;
    __syncthreads();
    if (tid < 32) {
        float t = (tid < 8) ? red[tid] : 0.f;
#pragma unroll
        for (int o = 4; o > 0; o >>= 1) t += __shfl_down_sync(0xffffffffu, t, o);
        if (tid == 0) sRstd = rsqrtf(t * (1.f / HIDDIM) + 1e-12f);
    }
    __syncthreads();
    const float rstd = sRstd;

#pragma unroll
    for (int i = 0; i < 3; i++) {
        int c = tid + i * 256;
        y[(size_t)row * HIDDIM + c] = g[c] * (v[i] - mean) * rstd + bb[c];
    }
}

// ---------------- launch ----------------------------------------------------
extern "C" void kernel_launch(void* const* d_in, const int* in_sizes, int n_in,
                              void* d_out, int out_size)
{
    const float* hs    = (const float*)d_in[0];
    const float* amask = (const float*)d_in[1];
    const float* Wq = (const float*)d_in[2];  const float* bq = (const float*)d_in[3];
    const float* Wk = (const float*)d_in[4];  const float* bk = (const float*)d_in[5];
    const float* Wv = (const float*)d_in[6];  const float* bv = (const float*)d_in[7];
    const float* Wo = (const float*)d_in[8];  const float* bo = (const float*)d_in[9];
    const float* g1 = (const float*)d_in[10]; const float* b1 = (const float*)d_in[11];
    const float* Wi = (const float*)d_in[12]; const float* bi = (const float*)d_in[13];
    const float* Wd = (const float*)d_in[14]; const float* bd = (const float*)d_in[15];
    const float* g2 = (const float*)d_in[16]; const float* b2 = (const float*)d_in[17];
    float* out = (float*)d_out;

    float *q, *k, *v, *ctx, *t1, *attn, *inter, *t2;
    cudaGetSymbolAddress((void**)&q,     g_q);
    cudaGetSymbolAddress((void**)&k,     g_k);
    cudaGetSymbolAddress((void**)&v,     g_v);
    cudaGetSymbolAddress((void**)&ctx,   g_ctx);
    cudaGetSymbolAddress((void**)&t1,    g_t1);
    cudaGetSymbolAddress((void**)&attn,  g_attn);
    cudaGetSymbolAddress((void**)&inter, g_inter);
    cudaGetSymbolAddress((void**)&t2,    g_t2);

    cudaFuncSetAttribute(flash_attn_kernel,
                         cudaFuncAttributeMaxDynamicSharedMemorySize, FLASH_SMEM);

    const dim3 gHID((MROWS + BM - 1) / BM, HIDDIM / BN);    // 76 x 12
    const dim3 gINT((MROWS + BM - 1) / BM, INTERDIM / BN);  // 76 x 48

    // QKV projections -> [B,H,S,DH]
    sgemm_kernel<MODE_QKV><<<gHID, 256>>>(hs, Wq, bq, nullptr, q, HIDDIM, HIDDIM);
    sgemm_kernel<MODE_QKV><<<gHID, 256>>>(hs, Wk, bk, nullptr, k, HIDDIM, HIDDIM);
    sgemm_kernel<MODE_QKV><<<gHID, 256>>>(hs, Wv, bv, nullptr, v, HIDDIM, HIDDIM);

    // attention -> ctx [B,S,HID]
    dim3 gAtt((SEQ + QT - 1) / QT, NHEAD, BATCH);           // 19 x 12 x 8
    flash_attn_kernel<<<gAtt, 256, FLASH_SMEM>>>(q, k, v, amask, ctx);

    // O-proj + residual, then LN1
    sgemm_kernel<MODE_RES><<<gHID, 256>>>(ctx, Wo, bo, hs, t1, HIDDIM, HIDDIM);
    layernorm_kernel<<<MROWS, 256>>>(t1, g1, b1, attn);

    // FFN
    sgemm_kernel<MODE_GELU><<<gINT, 256>>>(attn, Wi, bi, nullptr, inter, HIDDIM, INTERDIM);
    sgemm_kernel<MODE_RES><<<gHID, 256>>>(inter, Wd, bd, attn, t2, INTERDIM, HIDDIM);
    layernorm_kernel<<<MROWS, 256>>>(t2, g2, b2, out);
}

// round 5
// speedup vs baseline: 1.8236x; 1.8236x over previous
#include <cuda_runtime.h>
#include <math.h>
#include <stdint.h>

#define BATCH 8
#define SEQ 1213
#define NHEAD 12
#define DHEAD 64
#define HIDDIM 768
#define INTERDIM 3072
#define MROWS (BATCH*SEQ)      // 9704
#define NLEAD 12

// ---------------- scratch (static device globals; no allocation allowed) ----
__device__ float g_q[(size_t)BATCH*NHEAD*SEQ*DHEAD];
__device__ float g_k[(size_t)BATCH*NHEAD*SEQ*DHEAD];
__device__ float g_v[(size_t)BATCH*NHEAD*SEQ*DHEAD];
__device__ float g_ctx[(size_t)MROWS*HIDDIM];
__device__ float g_t1[(size_t)MROWS*HIDDIM];
__device__ float g_attn[(size_t)MROWS*HIDDIM];
__device__ float g_inter[(size_t)MROWS*INTERDIM];
__device__ float g_t2[(size_t)MROWS*HIDDIM];

// ============================================================================
// TF32 tensor-core GEMM: C[M,N] = A[M,K] @ W[K,N] (+epilogue)
// BM=128, BN=64, BK=32, 256 threads (8 warps in 4x2), warp tile 32x32,
// mma.sync.m16n8k8 tf32, fp32 accumulate.
// ============================================================================
#define GBM 128
#define GBN 64
#define GBK 32
#define ASTRIDE 36   // GBK + 4  -> conflict-free A fragment loads
#define BSTRIDE 72   // GBN + 8  -> conflict-free B fragment loads

enum { MODE_QKV = 0, MODE_RES = 1, MODE_GELU = 2 };

__device__ __forceinline__ unsigned f2tf32(float x) {
    unsigned r;
    asm("cvt.rna.tf32.f32 %0, %1;" : "=r"(r) : "f"(x));
    return r;
}

__device__ __forceinline__ void mma_tf32(float* c, const unsigned* a, const unsigned* b) {
    asm("mma.sync.aligned.m16n8k8.row.col.f32.tf32.tf32.f32 "
        "{%0,%1,%2,%3}, {%4,%5,%6,%7}, {%8,%9}, {%0,%1,%2,%3};"
        : "+f"(c[0]), "+f"(c[1]), "+f"(c[2]), "+f"(c[3])
        : "r"(a[0]), "r"(a[1]), "r"(a[2]), "r"(a[3]), "r"(b[0]), "r"(b[1]));
}

template<int MODE>
__global__ __launch_bounds__(256)
void mma_gemm_kernel(const float* __restrict__ A, const float* __restrict__ W,
                     const float* __restrict__ bias, const float* __restrict__ Rsd,
                     float* __restrict__ out, int K, int N)
{
    __shared__ float As[GBM][ASTRIDE];
    __shared__ float Bs[GBK][BSTRIDE];

    const int tid  = threadIdx.x;
    const int warp = tid >> 5;
    const int lane = tid & 31;
    const int wm   = warp >> 1;        // 0..3
    const int wn   = warp & 1;         // 0..1
    const int lrow = lane >> 2;        // 0..7
    const int lcol = lane & 3;         // 0..3
    const int m0   = blockIdx.x * GBM;
    const int n0   = blockIdx.y * GBN;

    float acc[2][4][4];
#pragma unroll
    for (int i = 0; i < 2; i++)
#pragma unroll
        for (int j = 0; j < 4; j++)
#pragma unroll
            for (int r = 0; r < 4; r++) acc[i][j][r] = 0.f;

    for (int k0 = 0; k0 < K; k0 += GBK) {
        // ---- stage A tile (convert to tf32): 128x32, 4 passes of float4 ----
#pragma unroll
        for (int p = 0; p < 4; p++) {
            int r = (tid >> 3) + p * 32;
            int c = (tid & 7) * 4;
            float4 v = make_float4(0.f, 0.f, 0.f, 0.f);
            if (m0 + r < MROWS)
                v = *reinterpret_cast<const float4*>(A + (size_t)(m0 + r) * K + k0 + c);
            uint4 t;
            t.x = f2tf32(v.x); t.y = f2tf32(v.y); t.z = f2tf32(v.z); t.w = f2tf32(v.w);
            *reinterpret_cast<uint4*>(&As[r][c]) = t;
        }
        // ---- stage B tile: 32x64, 2 passes of float4 ----
#pragma unroll
        for (int p = 0; p < 2; p++) {
            int r = (tid >> 4) + p * 16;
            int c = (tid & 15) * 4;
            float4 v = *reinterpret_cast<const float4*>(W + (size_t)(k0 + r) * N + n0 + c);
            uint4 t;
            t.x = f2tf32(v.x); t.y = f2tf32(v.y); t.z = f2tf32(v.z); t.w = f2tf32(v.w);
            *reinterpret_cast<uint4*>(&Bs[r][c]) = t;
        }
        __syncthreads();

#pragma unroll
        for (int kk = 0; kk < GBK; kk += 8) {
            unsigned a[2][4], b[4][2];
#pragma unroll
            for (int i = 0; i < 2; i++) {
                int r = wm * 32 + i * 16 + lrow;
                a[i][0] = __float_as_uint(As[r    ][kk + lcol    ]);
                a[i][1] = __float_as_uint(As[r + 8][kk + lcol    ]);
                a[i][2] = __float_as_uint(As[r    ][kk + lcol + 4]);
                a[i][3] = __float_as_uint(As[r + 8][kk + lcol + 4]);
            }
#pragma unroll
            for (int j = 0; j < 4; j++) {
                int c = wn * 32 + j * 8 + lrow;
                b[j][0] = __float_as_uint(Bs[kk + lcol    ][c]);
                b[j][1] = __float_as_uint(Bs[kk + lcol + 4][c]);
            }
#pragma unroll
            for (int i = 0; i < 2; i++)
#pragma unroll
                for (int j = 0; j < 4; j++)
                    mma_tf32(acc[i][j], a[i], b[j]);
        }
        __syncthreads();
    }

    // ---- epilogue: c0/c1 -> row base, c2/c3 -> row base+8; cols (lcol*2, +1) ----
#pragma unroll
    for (int i = 0; i < 2; i++) {
#pragma unroll
        for (int rr = 0; rr < 2; rr++) {
            const int m = m0 + wm * 32 + i * 16 + lrow + rr * 8;
            if (m >= MROWS) continue;
#pragma unroll
            for (int j = 0; j < 4; j++) {
                const int nloc = wn * 32 + j * 8 + lcol * 2;
                const int n = n0 + nloc;
                const float2 b2 = *reinterpret_cast<const float2*>(bias + n);
                float x0 = acc[i][j][rr * 2 + 0] + b2.x;
                float x1 = acc[i][j][rr * 2 + 1] + b2.y;

                if (MODE == MODE_QKV) {
                    const int h = n0 >> 6;            // GBN == DHEAD
                    const int bb = m / SEQ, srow = m % SEQ;
                    float2 o = make_float2(x0, x1);
                    *reinterpret_cast<float2*>(
                        out + (((size_t)bb * NHEAD + h) * SEQ + srow) * DHEAD + nloc) = o;
                } else if (MODE == MODE_RES) {
                    const float2 r2 = *reinterpret_cast<const float2*>(Rsd + (size_t)m * N + n);
                    float2 o = make_float2(x0 + r2.x, x1 + r2.y);
                    *reinterpret_cast<float2*>(out + (size_t)m * N + n) = o;
                } else { // MODE_GELU
                    float2 o;
                    o.x = 0.5f * x0 * (1.f + erff(x0 * 0.70710678118654752f));
                    o.y = 0.5f * x1 * (1.f + erff(x1 * 0.70710678118654752f));
                    *reinterpret_cast<float2*>(out + (size_t)m * N + n) = o;
                }
            }
        }
    }
}

// ============================================================================
// Flash attention (fp32, 64x64 tiles, register online softmax)
// ============================================================================
#define QT 64
#define KT 64
#define FPAD 68
#define FLASH_SMEM (4 * 64 * FPAD * 4)   // sQt, sKt, sV, sP = 69632 bytes

__global__ __launch_bounds__(256)
void flash_attn_kernel(const float* __restrict__ Q, const float* __restrict__ Kg,
                       const float* __restrict__ Vg, const float* __restrict__ amask,
                       float* __restrict__ ctx)
{
    extern __shared__ float sm[];
    float* sQt = sm;                       // [d][q]
    float* sKt = sQt + 64 * FPAD;          // [d][k]
    float* sV  = sKt + 64 * FPAD;          // [k][d]
    float* sP  = sV  + 64 * FPAD;          // [q][k]  (exp'd probabilities)

    const int qt = blockIdx.x;
    const int h  = blockIdx.y;
    const int b  = blockIdx.z;
    const int tid = threadIdx.x;
    const int tx = tid & 15;               // -> k (scores) / d (PV)
    const int ty = tid >> 4;               // -> q
    const size_t base = ((size_t)b * NHEAD + h) * SEQ * DHEAD;
    const int q0 = qt * QT;

    // load Q tile, transposed to [d][q]
    for (int s = tid; s < 64 * 16; s += 256) {
        int q = s >> 4;
        int dq = (s & 15) * 4;
        float4 v = make_float4(0.f, 0.f, 0.f, 0.f);
        if (q0 + q < SEQ)
            v = *reinterpret_cast<const float4*>(Q + base + (size_t)(q0 + q) * DHEAD + dq);
        sQt[(dq + 0) * FPAD + q] = v.x;
        sQt[(dq + 1) * FPAD + q] = v.y;
        sQt[(dq + 2) * FPAD + q] = v.z;
        sQt[(dq + 3) * FPAD + q] = v.w;
    }

    float m_run[4], l_run[4], acc[4][4];
#pragma unroll
    for (int i = 0; i < 4; i++) {
        m_run[i] = -1e30f; l_run[i] = 0.f;
#pragma unroll
        for (int j = 0; j < 4; j++) acc[i][j] = 0.f;
    }

    const int nkt = (SEQ + KT - 1) / KT;   // 19
    for (int kt = 0; kt < nkt; kt++) {
        const int k0 = kt * KT;
        __syncthreads();                   // prev PV done before overwriting sKt/sV
        for (int s = tid; s < 64 * 16; s += 256) {
            int k = s >> 4;
            int dq = (s & 15) * 4;
            float4 kv = make_float4(0.f, 0.f, 0.f, 0.f);
            float4 vv = make_float4(0.f, 0.f, 0.f, 0.f);
            if (k0 + k < SEQ) {
                kv = *reinterpret_cast<const float4*>(Kg + base + (size_t)(k0 + k) * DHEAD + dq);
                vv = *reinterpret_cast<const float4*>(Vg + base + (size_t)(k0 + k) * DHEAD + dq);
            }
            sKt[(dq + 0) * FPAD + k] = kv.x;
            sKt[(dq + 1) * FPAD + k] = kv.y;
            sKt[(dq + 2) * FPAD + k] = kv.z;
            sKt[(dq + 3) * FPAD + k] = kv.w;
            *reinterpret_cast<float4*>(&sV[k * FPAD + dq]) = vv;
        }
        __syncthreads();

        // scores S = Q @ K^T (4x4 micro-tile per thread)
        float sc[4][4];
#pragma unroll
        for (int i = 0; i < 4; i++)
#pragma unroll
            for (int j = 0; j < 4; j++) sc[i][j] = 0.f;
#pragma unroll 8
        for (int d = 0; d < 64; d++) {
            float q4[4], k4[4];
            *reinterpret_cast<float4*>(q4) = *reinterpret_cast<float4*>(&sQt[d * FPAD + ty * 4]);
            *reinterpret_cast<float4*>(k4) = *reinterpret_cast<float4*>(&sKt[d * FPAD + tx * 4]);
#pragma unroll
            for (int i = 0; i < 4; i++)
#pragma unroll
                for (int j = 0; j < 4; j++)
                    sc[i][j] += q4[i] * k4[j];
        }

        // masks, in registers
#pragma unroll
        for (int j = 0; j < 4; j++) {
            const int kg = k0 + tx * 4 + j;
            const float am = (kg < SEQ) ? amask[(size_t)b * SEQ + kg] : 0.f;
#pragma unroll
            for (int i = 0; i < 4; i++) {
                const int qg = q0 + ty * 4 + i;
                float val;
                if (kg >= SEQ) {
                    val = -1e30f;
                } else {
                    val = sc[i][j] * 0.125f + am;
                    if (qg == 0) {
                        if (kg >= 1 && kg < 1 + NLEAD) val += -99999.f;
                    } else if (qg >= 1 && qg <= NLEAD) {
                        int start = NLEAD + 1 + 100 * (qg - 1);
                        bool inb = (kg >= start) && (kg < start + 100);
                        if (!inb) val += -99999.f;
                    }
                }
                sc[i][j] = val;
            }
        }

        // register online softmax: reduce across the 16 lanes sharing ty
        float fac[4], p[4][4];
#pragma unroll
        for (int i = 0; i < 4; i++) {
            float mt = fmaxf(fmaxf(sc[i][0], sc[i][1]), fmaxf(sc[i][2], sc[i][3]));
#pragma unroll
            for (int off = 8; off >= 1; off >>= 1)
                mt = fmaxf(mt, __shfl_xor_sync(0xffffffffu, mt, off));
            const float mnew = fmaxf(m_run[i], mt);
            fac[i] = __expf(m_run[i] - mnew);
            m_run[i] = mnew;
            float ls = 0.f;
#pragma unroll
            for (int j = 0; j < 4; j++) {
                p[i][j] = __expf(sc[i][j] - mnew);
                ls += p[i][j];
            }
#pragma unroll
            for (int off = 8; off >= 1; off >>= 1)
                ls += __shfl_xor_sync(0xffffffffu, ls, off);
            l_run[i] = l_run[i] * fac[i] + ls;
        }

        // store P (exp'd) once: sP[q][k], float4
#pragma unroll
        for (int i = 0; i < 4; i++)
            *reinterpret_cast<float4*>(&sP[(ty * 4 + i) * FPAD + tx * 4]) =
                make_float4(p[i][0], p[i][1], p[i][2], p[i][3]);
        __syncthreads();

        // rescale accumulators, then acc += P @ V
#pragma unroll
        for (int i = 0; i < 4; i++)
#pragma unroll
            for (int j = 0; j < 4; j++) acc[i][j] *= fac[i];

#pragma unroll 8
        for (int k = 0; k < KT; k++) {
            float v4[4];
            *reinterpret_cast<float4*>(v4) = *reinterpret_cast<float4*>(&sV[k * FPAD + tx * 4]);
#pragma unroll
            for (int i = 0; i < 4; i++) {
                const float pk = sP[(ty * 4 + i) * FPAD + k];   // broadcast across 16 lanes
#pragma unroll
                for (int j = 0; j < 4; j++)
                    acc[i][j] += pk * v4[j];
            }
        }
    }

    // write ctx in [B, S, HID]
#pragma unroll
    for (int i = 0; i < 4; i++) {
        const int qg = q0 + ty * 4 + i;
        if (qg < SEQ) {
            const float invl = 1.f / l_run[i];
            float4 o;
            o.x = acc[i][0] * invl;
            o.y = acc[i][1] * invl;
            o.z = acc[i][2] * invl;
            o.w = acc[i][3] * invl;
            *reinterpret_cast<float4*>(
                ctx + ((size_t)b * SEQ + qg) * HIDDIM + h * DHEAD + tx * 4) = o;
        }
    }
}

// ---------------- LayerNorm (one block per row, HID=768, 256 threads) -------
__global__ __launch_bounds__(256)
void layernorm_kernel(const float* __restrict__ x, const float* __restrict__ g,
                      const float* __restrict__ bb, float* __restrict__ y)
{
    __shared__ float red[8];
    __shared__ float sMean, sRstd;
    const int row = blockIdx.x;
    const int tid = threadIdx.x;
    const float* xr = x + (size_t)row * HIDDIM;

    float v[3];
    float sum = 0.f;
#pragma unroll
    for (int i = 0; i < 3; i++) { v[i] = xr[tid + i * 256]; sum += v[i]; }

#pragma unroll
    for (int o = 16; o > 0; o >>= 1) sum += __shfl_down_sync(0xffffffffu, sum, o);
    if ((tid & 31) == 0) red[tid >> 5] = sum;
    __syncthreads();
    if (tid < 32) {
        float t = (tid < 8) ? red[tid] : 0.f;
#pragma unroll
        for (int o = 4; o > 0; o >>= 1) t += __shfl_down_sync(0xffffffffu, t, o);
        if (tid == 0) sMean = t * (1.f / HIDDIM);
    }
    __syncthreads();
    const float mean = sMean;

    float sq = 0.f;
#pragma unroll
    for (int i = 0; i < 3; i++) { float d = v[i] - mean; sq += d * d; }
#pragma unroll
    for (int o = 16; o > 0; o >>= 1) sq += __shfl_down_sync(0xffffffffu, sq, o);
    __syncthreads();
    if ((tid & 31) == 0) red[tid >> 5] = sq;
    __syncthreads();
    if (tid < 32) {
        float t = (tid < 8) ? red[tid] : 0.f;
#pragma unroll
        for (int o = 4; o > 0; o >>= 1) t += __shfl_down_sync(0xffffffffu, t, o);
        if (tid == 0) sRstd = rsqrtf(t * (1.f / HIDDIM) + 1e-12f);
    }
    __syncthreads();
    const float rstd = sRstd;

#pragma unroll
    for (int i = 0; i < 3; i++) {
        int c = tid + i * 256;
        y[(size_t)row * HIDDIM + c] = g[c] * (v[i] - mean) * rstd + bb[c];
    }
}

// ---------------- launch ----------------------------------------------------
extern "C" void kernel_launch(void* const* d_in, const int* in_sizes, int n_in,
                              void* d_out, int out_size)
{
    const float* hs    = (const float*)d_in[0];
    const float* amask = (const float*)d_in[1];
    const float* Wq = (const float*)d_in[2];  const float* bq = (const float*)d_in[3];
    const float* Wk = (const float*)d_in[4];  const float* bk = (const float*)d_in[5];
    const float* Wv = (const float*)d_in[6];  const float* bv = (const float*)d_in[7];
    const float* Wo = (const float*)d_in[8];  const float* bo = (const float*)d_in[9];
    const float* g1 = (const float*)d_in[10]; const float* b1 = (const float*)d_in[11];
    const float* Wi = (const float*)d_in[12]; const float* bi = (const float*)d_in[13];
    const float* Wd = (const float*)d_in[14]; const float* bd = (const float*)d_in[15];
    const float* g2 = (const float*)d_in[16]; const float* b2 = (const float*)d_in[17];
    float* out = (float*)d_out;

    float *q, *k, *v, *ctx, *t1, *attn, *inter, *t2;
    cudaGetSymbolAddress((void**)&q,     g_q);
    cudaGetSymbolAddress((void**)&k,     g_k);
    cudaGetSymbolAddress((void**)&v,     g_v);
    cudaGetSymbolAddress((void**)&ctx,   g_ctx);
    cudaGetSymbolAddress((void**)&t1,    g_t1);
    cudaGetSymbolAddress((void**)&attn,  g_attn);
    cudaGetSymbolAddress((void**)&inter, g_inter);
    cudaGetSymbolAddress((void**)&t2,    g_t2);

    cudaFuncSetAttribute(flash_attn_kernel,
                         cudaFuncAttributeMaxDynamicSharedMemorySize, FLASH_SMEM);

    const dim3 gHID((MROWS + GBM - 1) / GBM, HIDDIM / GBN);    // 76 x 12
    const dim3 gINT((MROWS + GBM - 1) / GBM, INTERDIM / GBN);  // 76 x 48

    // QKV projections -> [B,H,S,DH]
    mma_gemm_kernel<MODE_QKV><<<gHID, 256>>>(hs, Wq, bq, nullptr, q, HIDDIM, HIDDIM);
    mma_gemm_kernel<MODE_QKV><<<gHID, 256>>>(hs, Wk, bk, nullptr, k, HIDDIM, HIDDIM);
    mma_gemm_kernel<MODE_QKV><<<gHID, 256>>>(hs, Wv, bv, nullptr, v, HIDDIM, HIDDIM);

    // attention -> ctx [B,S,HID]
    dim3 gAtt((SEQ + QT - 1) / QT, NHEAD, BATCH);              // 19 x 12 x 8
    flash_attn_kernel<<<gAtt, 256, FLASH_SMEM>>>(q, k, v, amask, ctx);

    // O-proj + residual, then LN1
    mma_gemm_kernel<MODE_RES><<<gHID, 256>>>(ctx, Wo, bo, hs, t1, HIDDIM, HIDDIM);
    layernorm_kernel<<<MROWS, 256>>>(t1, g1, b1, attn);

    // FFN
    mma_gemm_kernel<MODE_GELU><<<gINT, 256>>>(attn, Wi, bi, nullptr, inter, HIDDIM, INTERDIM);
    mma_gemm_kernel<MODE_RES><<<gHID, 256>>>(inter, Wd, bd, attn, t2, INTERDIM, HIDDIM);
    layernorm_kernel<<<MROWS, 256>>>(t2, g2, b2, out);
}

// round 7
// speedup vs baseline: 2.3758x; 1.3028x over previous
#include <cuda_runtime.h>
#include <math.h>
#include <stdint.h>

#define BATCH 8
#define SEQ 1213
#define NHEAD 12
#define DHEAD 64
#define HIDDIM 768
#define INTERDIM 3072
#define MROWS (BATCH*SEQ)      // 9704
#define NLEAD 12

// ---------------- scratch (static device globals; no allocation allowed) ----
__device__ float g_q[(size_t)BATCH*NHEAD*SEQ*DHEAD];
__device__ float g_k[(size_t)BATCH*NHEAD*SEQ*DHEAD];
__device__ float g_v[(size_t)BATCH*NHEAD*SEQ*DHEAD];
__device__ float g_ctx[(size_t)MROWS*HIDDIM];
__device__ float g_t1[(size_t)MROWS*HIDDIM];
__device__ float g_attn[(size_t)MROWS*HIDDIM];
__device__ float g_inter[(size_t)MROWS*INTERDIM];
__device__ float g_t2[(size_t)MROWS*HIDDIM];

__device__ __forceinline__ unsigned f2tf32(float x) {
    unsigned r;
    asm("cvt.rna.tf32.f32 %0, %1;" : "=r"(r) : "f"(x));
    return r;
}

__device__ __forceinline__ void mma_tf32(float* c, const unsigned* a, const unsigned* b) {
    asm("mma.sync.aligned.m16n8k8.row.col.f32.tf32.tf32.f32 "
        "{%0,%1,%2,%3}, {%4,%5,%6,%7}, {%8,%9}, {%0,%1,%2,%3};"
        : "+f"(c[0]), "+f"(c[1]), "+f"(c[2]), "+f"(c[3])
        : "r"(a[0]), "r"(a[1]), "r"(a[2]), "r"(a[3]), "r"(b[0]), "r"(b[1]));
}

// ============================================================================
// TF32 tensor-core GEMM, double-buffered + register-prefetch pipeline.
// C[M,N] = A[M,K] @ W[K,N] (+epilogue). BM=128, BN=64, BK=32, 256 threads,
// 8 warps 4x2, warp tile 32x32.
// ============================================================================
#define GBM 128
#define GBN 64
#define GBK 32
#define ASTRIDE 36
#define BSTRIDE 72
#define GEMM_SMEM ((2*GBM*ASTRIDE + 2*GBK*BSTRIDE) * 4)   // 55296 bytes

enum { MODE_QKV = 0, MODE_RES = 1, MODE_GELU = 2 };

template<int MODE>
__global__ __launch_bounds__(256)
void mma_gemm_kernel(const float* __restrict__ A, const float* __restrict__ W,
                     const float* __restrict__ bias, const float* __restrict__ Rsd,
                     float* __restrict__ out, int K, int N)
{
    extern __shared__ float gsm[];
    float* As = gsm;                               // [2][GBM][ASTRIDE]
    float* Bs = gsm + 2 * GBM * ASTRIDE;           // [2][GBK][BSTRIDE]

    const int tid  = threadIdx.x;
    const int warp = tid >> 5;
    const int lane = tid & 31;
    const int wm   = warp >> 1;
    const int wn   = warp & 1;
    const int lrow = lane >> 2;
    const int lcol = lane & 3;
    const int m0   = blockIdx.x * GBM;
    const int n0   = blockIdx.y * GBN;

    const int arow = tid >> 3;          // + p*32, p<4
    const int acol = (tid & 7) * 4;
    const int brow = tid >> 4;          // + p*16, p<2
    const int bcol = (tid & 15) * 4;

    float acc[2][4][4];
#pragma unroll
    for (int i = 0; i < 2; i++)
#pragma unroll
        for (int j = 0; j < 4; j++)
#pragma unroll
            for (int r = 0; r < 4; r++) acc[i][j][r] = 0.f;

    float4 aR[4], bR[2];

    auto ldg_tiles = [&](int k0) {
#pragma unroll
        for (int p = 0; p < 4; p++) {
            int m = m0 + arow + p * 32;
            aR[p] = make_float4(0.f, 0.f, 0.f, 0.f);
            if (m < MROWS)
                aR[p] = *reinterpret_cast<const float4*>(A + (size_t)m * K + k0 + acol);
        }
#pragma unroll
        for (int p = 0; p < 2; p++)
            bR[p] = *reinterpret_cast<const float4*>(W + (size_t)(k0 + brow + p * 16) * N + n0 + bcol);
    };
    auto sts_tiles = [&](int buf) {
        float* Ab = As + buf * GBM * ASTRIDE;
        float* Bb = Bs + buf * GBK * BSTRIDE;
#pragma unroll
        for (int p = 0; p < 4; p++) {
            uint4 t;
            t.x = f2tf32(aR[p].x); t.y = f2tf32(aR[p].y);
            t.z = f2tf32(aR[p].z); t.w = f2tf32(aR[p].w);
            *reinterpret_cast<uint4*>(&Ab[(arow + p * 32) * ASTRIDE + acol]) = t;
        }
#pragma unroll
        for (int p = 0; p < 2; p++) {
            uint4 t;
            t.x = f2tf32(bR[p].x); t.y = f2tf32(bR[p].y);
            t.z = f2tf32(bR[p].z); t.w = f2tf32(bR[p].w);
            *reinterpret_cast<uint4*>(&Bb[(brow + p * 16) * BSTRIDE + bcol]) = t;
        }
    };

    const int nkt = K / GBK;
    ldg_tiles(0);
    sts_tiles(0);
    __syncthreads();

    for (int kt = 0; kt < nkt; kt++) {
        const int buf = kt & 1;
        if (kt + 1 < nkt) ldg_tiles((kt + 1) * GBK);

        const float* Ab = As + buf * GBM * ASTRIDE;
        const float* Bb = Bs + buf * GBK * BSTRIDE;
#pragma unroll
        for (int kk = 0; kk < GBK; kk += 8) {
            unsigned a[2][4], b[4][2];
#pragma unroll
            for (int i = 0; i < 2; i++) {
                int r = wm * 32 + i * 16 + lrow;
                a[i][0] = __float_as_uint(Ab[ r      * ASTRIDE + kk + lcol    ]);
                a[i][1] = __float_as_uint(Ab[(r + 8) * ASTRIDE + kk + lcol    ]);
                a[i][2] = __float_as_uint(Ab[ r      * ASTRIDE + kk + lcol + 4]);
                a[i][3] = __float_as_uint(Ab[(r + 8) * ASTRIDE + kk + lcol + 4]);
            }
#pragma unroll
            for (int j = 0; j < 4; j++) {
                int c = wn * 32 + j * 8 + lrow;
                b[j][0] = __float_as_uint(Bb[(kk + lcol    ) * BSTRIDE + c]);
                b[j][1] = __float_as_uint(Bb[(kk + lcol + 4) * BSTRIDE + c]);
            }
#pragma unroll
            for (int i = 0; i < 2; i++)
#pragma unroll
                for (int j = 0; j < 4; j++)
                    mma_tf32(acc[i][j], a[i], b[j]);
        }

        if (kt + 1 < nkt) sts_tiles(buf ^ 1);
        __syncthreads();
    }

    // ---- epilogue ----
#pragma unroll
    for (int i = 0; i < 2; i++) {
#pragma unroll
        for (int rr = 0; rr < 2; rr++) {
            const int m = m0 + wm * 32 + i * 16 + lrow + rr * 8;
            if (m >= MROWS) continue;
#pragma unroll
            for (int j = 0; j < 4; j++) {
                const int nloc = wn * 32 + j * 8 + lcol * 2;
                const int n = n0 + nloc;
                const float2 b2 = *reinterpret_cast<const float2*>(bias + n);
                float x0 = acc[i][j][rr * 2 + 0] + b2.x;
                float x1 = acc[i][j][rr * 2 + 1] + b2.y;

                if (MODE == MODE_QKV) {
                    const int h = n0 >> 6;
                    const int bb = m / SEQ, srow = m % SEQ;
                    *reinterpret_cast<float2*>(
                        out + (((size_t)bb * NHEAD + h) * SEQ + srow) * DHEAD + nloc) =
                        make_float2(x0, x1);
                } else if (MODE == MODE_RES) {
                    const float2 r2 = *reinterpret_cast<const float2*>(Rsd + (size_t)m * N + n);
                    *reinterpret_cast<float2*>(out + (size_t)m * N + n) =
                        make_float2(x0 + r2.x, x1 + r2.y);
                } else {
                    float2 o;
                    o.x = 0.5f * x0 * (1.f + erff(x0 * 0.70710678118654752f));
                    o.y = 0.5f * x1 * (1.f + erff(x1 * 0.70710678118654752f));
                    *reinterpret_cast<float2*>(out + (size_t)m * N + n) = o;
                }
            }
        }
    }
}

// ============================================================================
// Flash attention: tf32 mma for QK^T and PV. QT=128, KT=64, 8 warps,
// each warp owns 16 q-rows. Register softmax via 4-lane shfl reductions.
// ============================================================================
#define AQT 128
#define AKT 64
#define QPAD 68
#define KPAD 68
#define VPAD 72
#define PPAD 68
#define FLASH_SMEM ((AQT*QPAD + AKT*KPAD + AKT*VPAD + AQT*PPAD) * 4)  // 105472

__global__ __launch_bounds__(256)
void flash_attn_kernel(const float* __restrict__ Q, const float* __restrict__ Kg,
                       const float* __restrict__ Vg, const float* __restrict__ amask,
                       float* __restrict__ ctx)
{
    extern __shared__ float sm[];
    float* sQ = sm;                        // [128][QPAD]  tf32(Q * 0.125)
    float* sK = sQ + AQT * QPAD;           // [64][KPAD]   tf32(K)
    float* sV = sK + AKT * KPAD;           // [64][VPAD]   tf32(V)
    float* sP = sV + AKT * VPAD;           // [128][PPAD]  tf32(P), per-warp private rows

    const int tid  = threadIdx.x;
    const int warp = tid >> 5;
    const int lane = tid & 31;
    const int g    = lane >> 2;            // fragment group (row within tile)
    const int t4   = lane & 3;
    const int qb   = warp * 16;
    const int q0   = blockIdx.x * AQT;
    const int h    = blockIdx.y;
    const int b    = blockIdx.z;
    const size_t base = ((size_t)b * NHEAD + h) * SEQ * DHEAD;

    // ---- stage Q (scaled by 1/sqrt(DH) = 0.125, tf32) ----
#pragma unroll
    for (int p = 0; p < 8; p++) {
        const int row = (tid >> 4) + p * 16;
        const int col = (tid & 15) * 4;
        float4 v = make_float4(0.f, 0.f, 0.f, 0.f);
        if (q0 + row < SEQ)
            v = *reinterpret_cast<const float4*>(Q + base + (size_t)(q0 + row) * DHEAD + col);
        uint4 t;
        t.x = f2tf32(v.x * 0.125f); t.y = f2tf32(v.y * 0.125f);
        t.z = f2tf32(v.z * 0.125f); t.w = f2tf32(v.w * 0.125f);
        *reinterpret_cast<uint4*>(&sQ[row * QPAD + col]) = t;
    }

    float m_run[2] = {-1e30f, -1e30f};
    float l_run[2] = {0.f, 0.f};
    float o[8][4];
#pragma unroll
    for (int j = 0; j < 8; j++)
#pragma unroll
        for (int r = 0; r < 4; r++) o[j][r] = 0.f;

    const bool lead_warp = (q0 == 0 && warp == 0);

    const int nkt = (SEQ + AKT - 1) / AKT;   // 19
    for (int kt = 0; kt < nkt; kt++) {
        const int k0 = kt * AKT;
        __syncthreads();   // all warps done with previous sK/sV

        // ---- stage K, V (tf32) ----
#pragma unroll
        for (int p = 0; p < 4; p++) {
            const int row = (tid >> 4) + p * 16;
            const int col = (tid & 15) * 4;
            float4 kv = make_float4(0.f, 0.f, 0.f, 0.f);
            float4 vv = make_float4(0.f, 0.f, 0.f, 0.f);
            if (k0 + row < SEQ) {
                kv = *reinterpret_cast<const float4*>(Kg + base + (size_t)(k0 + row) * DHEAD + col);
                vv = *reinterpret_cast<const float4*>(Vg + base + (size_t)(k0 + row) * DHEAD + col);
            }
            uint4 tk, tv;
            tk.x = f2tf32(kv.x); tk.y = f2tf32(kv.y); tk.z = f2tf32(kv.z); tk.w = f2tf32(kv.w);
            tv.x = f2tf32(vv.x); tv.y = f2tf32(vv.y); tv.z = f2tf32(vv.z); tv.w = f2tf32(vv.w);
            *reinterpret_cast<uint4*>(&sK[row * KPAD + col]) = tk;
            *reinterpret_cast<uint4*>(&sV[row * VPAD + col]) = tv;
        }
        __syncthreads();

        // ---- S = Q @ K^T : warp tile 16 x 64, 8 n-frags, k over 64 ----
        float sc[8][4];
#pragma unroll
        for (int j = 0; j < 8; j++)
#pragma unroll
            for (int r = 0; r < 4; r++) sc[j][r] = 0.f;

#pragma unroll
        for (int kk = 0; kk < 8; kk++) {
            unsigned a[4];
            const float* qr = &sQ[(qb + g) * QPAD + kk * 8 + t4];
            a[0] = __float_as_uint(qr[0]);
            a[1] = __float_as_uint(qr[8 * QPAD]);
            a[2] = __float_as_uint(qr[4]);
            a[3] = __float_as_uint(qr[8 * QPAD + 4]);
#pragma unroll
            for (int j = 0; j < 8; j++) {
                unsigned bb[2];
                const float* kr = &sK[(j * 8 + g) * KPAD + kk * 8 + t4];
                bb[0] = __float_as_uint(kr[0]);
                bb[1] = __float_as_uint(kr[4]);
                mma_tf32(sc[j], a, bb);
            }
        }

        // ---- masks (attention_mask + lead mask + OOB) ----
#pragma unroll
        for (int j = 0; j < 8; j++) {
#pragma unroll
            for (int e = 0; e < 2; e++) {
                const int cg = k0 + j * 8 + 2 * t4 + e;
                const float am = (cg < SEQ) ? __ldg(amask + (size_t)b * SEQ + cg) : 0.f;
#pragma unroll
                for (int rr = 0; rr < 2; rr++) {
                    float val = sc[j][rr * 2 + e] + am;
                    if (cg >= SEQ) val = -1e30f;
                    if (lead_warp) {
                        const int qg = qb + g + rr * 8;   // q0 == 0 here
                        if (qg == 0) {
                            if (cg >= 1 && cg < 1 + NLEAD) val -= 99999.f;
                        } else if (qg >= 1 && qg <= NLEAD) {
                            const int start = NLEAD + 1 + 100 * (qg - 1);
                            if (!(cg >= start && cg < start + 100)) val -= 99999.f;
                        }
                    }
                    sc[j][rr * 2 + e] = val;
                }
            }
        }

        // ---- online softmax per row half; rows live in 4-lane groups ----
#pragma unroll
        for (int rr = 0; rr < 2; rr++) {
            float mt = -1e30f;
#pragma unroll
            for (int j = 0; j < 8; j++)
                mt = fmaxf(mt, fmaxf(sc[j][rr * 2], sc[j][rr * 2 + 1]));
            mt = fmaxf(mt, __shfl_xor_sync(0xffffffffu, mt, 1));
            mt = fmaxf(mt, __shfl_xor_sync(0xffffffffu, mt, 2));
            const float mnew = fmaxf(m_run[rr], mt);
            const float fac = __expf(m_run[rr] - mnew);
            m_run[rr] = mnew;
            float ls = 0.f;
#pragma unroll
            for (int j = 0; j < 8; j++) {
                float p0 = __expf(sc[j][rr * 2    ] - mnew);
                float p1 = __expf(sc[j][rr * 2 + 1] - mnew);
                sc[j][rr * 2    ] = p0;
                sc[j][rr * 2 + 1] = p1;
                ls += p0 + p1;
            }
            ls += __shfl_xor_sync(0xffffffffu, ls, 1);
            ls += __shfl_xor_sync(0xffffffffu, ls, 2);
            l_run[rr] = l_run[rr] * fac + ls;
#pragma unroll
            for (int j = 0; j < 8; j++) {
                o[j][rr * 2    ] *= fac;
                o[j][rr * 2 + 1] *= fac;
            }
        }

        // ---- store P (tf32) to this warp's private sP rows ----
#pragma unroll
        for (int rr = 0; rr < 2; rr++)
#pragma unroll
            for (int j = 0; j < 8; j++) {
                uint2 u;
                u.x = f2tf32(sc[j][rr * 2]);
                u.y = f2tf32(sc[j][rr * 2 + 1]);
                *reinterpret_cast<uint2*>(
                    &sP[(qb + g + rr * 8) * PPAD + j * 8 + 2 * t4]) = u;
            }
        __syncwarp();   // sP rows are per-warp private — warp-level sync suffices

        // ---- O += P @ V : A = P[16 x 64], B = V[64 x 64] ----
#pragma unroll
        for (int kk = 0; kk < 8; kk++) {
            unsigned a[4];
            const float* pr = &sP[(qb + g) * PPAD + kk * 8 + t4];
            a[0] = __float_as_uint(pr[0]);
            a[1] = __float_as_uint(pr[8 * PPAD]);
            a[2] = __float_as_uint(pr[4]);
            a[3] = __float_as_uint(pr[8 * PPAD + 4]);
#pragma unroll
            for (int j = 0; j < 8; j++) {
                unsigned bb[2];
                const float* vr = &sV[(kk * 8 + t4) * VPAD + j * 8 + g];
                bb[0] = __float_as_uint(vr[0]);
                bb[1] = __float_as_uint(vr[4 * VPAD]);
                mma_tf32(o[j], a, bb);
            }
        }
    }

    // ---- epilogue: normalize and write ctx [B,S,HID] ----
#pragma unroll
    for (int rr = 0; rr < 2; rr++) {
        const int qg = q0 + qb + g + rr * 8;
        if (qg < SEQ) {
            const float inv = 1.f / l_run[rr];
#pragma unroll
            for (int j = 0; j < 8; j++) {
                float2 ov;
                ov.x = o[j][rr * 2    ] * inv;
                ov.y = o[j][rr * 2 + 1] * inv;
                *reinterpret_cast<float2*>(
                    ctx + ((size_t)b * SEQ + qg) * HIDDIM + h * DHEAD + j * 8 + 2 * t4) = ov;
            }
        }
    }
}

// ---------------- LayerNorm (one block per row, HID=768, 256 threads) -------
__global__ __launch_bounds__(256)
void layernorm_kernel(const float* __restrict__ x, const float* __restrict__ g,
                      const float* __restrict__ bb, float* __restrict__ y)
{
    __shared__ float red[8];
    __shared__ float sMean, sRstd;
    const int row = blockIdx.x;
    const int tid = threadIdx.x;
    const float* xr = x + (size_t)row * HIDDIM;

    float v[3];
    float sum = 0.f;
#pragma unroll
    for (int i = 0; i < 3; i++) { v[i] = xr[tid + i * 256]; sum += v[i]; }

#pragma unroll
    for (int o = 16; o > 0; o >>= 1) sum += __shfl_down_sync(0xffffffffu, sum, o);
    if ((tid & 31) == 0) red[tid >> 5] = sum;
    __syncthreads();
    if (tid < 32) {
        float t = (tid < 8) ? red[tid] : 0.f;
#pragma unroll
        for (int o = 4; o > 0; o >>= 1) t += __shfl_down_sync(0xffffffffu, t, o);
        if (tid == 0) sMean = t * (1.f / HIDDIM);
    }
    __syncthreads();
    const float mean = sMean;

    float sq = 0.f;
#pragma unroll
    for (int i = 0; i < 3; i++) { float d = v[i] - mean; sq += d * d; }
#pragma unroll
    for (int o = 16; o > 0; o >>= 1) sq += __shfl_down_sync(0xffffffffu, sq, o);
    __syncthreads();
    if ((tid & 31) == 0) red[tid >> 5] = sq;
    __syncthreads();
    if (tid < 32) {
        float t = (tid < 8) ? red[tid] : 0.f;
#pragma unroll
        for (int o = 4; o > 0; o >>= 1) t += __shfl_down_sync(0xffffffffu, t, o);
        if (tid == 0) sRstd = rsqrtf(t * (1.f / HIDDIM) + 1e-12f);
    }
    __syncthreads();
    const float rstd = sRstd;

#pragma unroll
    for (int i = 0; i < 3; i++) {
        int c = tid + i * 256;
        y[(size_t)row * HIDDIM + c] = g[c] * (v[i] - mean) * rstd + bb[c];
    }
}

// ---------------- launch ----------------------------------------------------
extern "C" void kernel_launch(void* const* d_in, const int* in_sizes, int n_in,
                              void* d_out, int out_size)
{
    const float* hs    = (const float*)d_in[0];
    const float* amask = (const float*)d_in[1];
    const float* Wq = (const float*)d_in[2];  const float* bq = (const float*)d_in[3];
    const float* Wk = (const float*)d_in[4];  const float* bk = (const float*)d_in[5];
    const float* Wv = (const float*)d_in[6];  const float* bv = (const float*)d_in[7];
    const float* Wo = (const float*)d_in[8];  const float* bo = (const float*)d_in[9];
    const float* g1 = (const float*)d_in[10]; const float* b1 = (const float*)d_in[11];
    const float* Wi = (const float*)d_in[12]; const float* bi = (const float*)d_in[13];
    const float* Wd = (const float*)d_in[14]; const float* bd = (const float*)d_in[15];
    const float* g2 = (const float*)d_in[16]; const float* b2 = (const float*)d_in[17];
    float* out = (float*)d_out;

    float *q, *k, *v, *ctx, *t1, *attn, *inter, *t2;
    cudaGetSymbolAddress((void**)&q,     g_q);
    cudaGetSymbolAddress((void**)&k,     g_k);
    cudaGetSymbolAddress((void**)&v,     g_v);
    cudaGetSymbolAddress((void**)&ctx,   g_ctx);
    cudaGetSymbolAddress((void**)&t1,    g_t1);
    cudaGetSymbolAddress((void**)&attn,  g_attn);
    cudaGetSymbolAddress((void**)&inter, g_inter);
    cudaGetSymbolAddress((void**)&t2,    g_t2);

    cudaFuncSetAttribute(flash_attn_kernel,
                         cudaFuncAttributeMaxDynamicSharedMemorySize, FLASH_SMEM);
    cudaFuncSetAttribute(mma_gemm_kernel<MODE_QKV>,
                         cudaFuncAttributeMaxDynamicSharedMemorySize, GEMM_SMEM);
    cudaFuncSetAttribute(mma_gemm_kernel<MODE_RES>,
                         cudaFuncAttributeMaxDynamicSharedMemorySize, GEMM_SMEM);
    cudaFuncSetAttribute(mma_gemm_kernel<MODE_GELU>,
                         cudaFuncAttributeMaxDynamicSharedMemorySize, GEMM_SMEM);

    const dim3 gHID((MROWS + GBM - 1) / GBM, HIDDIM / GBN);    // 76 x 12
    const dim3 gINT((MROWS + GBM - 1) / GBM, INTERDIM / GBN);  // 76 x 48

    // QKV projections -> [B,H,S,DH]
    mma_gemm_kernel<MODE_QKV><<<gHID, 256, GEMM_SMEM>>>(hs, Wq, bq, nullptr, q, HIDDIM, HIDDIM);
    mma_gemm_kernel<MODE_QKV><<<gHID, 256, GEMM_SMEM>>>(hs, Wk, bk, nullptr, k, HIDDIM, HIDDIM);
    mma_gemm_kernel<MODE_QKV><<<gHID, 256, GEMM_SMEM>>>(hs, Wv, bv, nullptr, v, HIDDIM, HIDDIM);

    // attention -> ctx [B,S,HID]
    dim3 gAtt((SEQ + AQT - 1) / AQT, NHEAD, BATCH);            // 10 x 12 x 8
    flash_attn_kernel<<<gAtt, 256, FLASH_SMEM>>>(q, k, v, amask, ctx);

    // O-proj + residual, then LN1
    mma_gemm_kernel<MODE_RES><<<gHID, 256, GEMM_SMEM>>>(ctx, Wo, bo, hs, t1, HIDDIM, HIDDIM);
    layernorm_kernel<<<MROWS, 256>>>(t1, g1, b1, attn);

    // FFN
    mma_gemm_kernel<MODE_GELU><<<gINT, 256, GEMM_SMEM>>>(attn, Wi, bi, nullptr, inter, HIDDIM, INTERDIM);
    mma_gemm_kernel<MODE_RES><<<gHID, 256, GEMM_SMEM>>>(inter, Wd, bd, attn, t2, INTERDIM, HIDDIM);
    layernorm_kernel<<<MROWS, 256>>>(t2, g2, b2, out);
}

// round 9
// speedup vs baseline: 3.1564x; 1.3286x over previous
#include <cuda_runtime.h>
#include <math.h>
#include <stdint.h>

#define BATCH 8
#define SEQ 1213
#define NHEAD 12
#define DHEAD 64
#define HIDDIM 768
#define INTERDIM 3072
#define MROWS (BATCH*SEQ)      // 9704
#define NLEAD 12

// ---------------- scratch (static device globals; no allocation allowed) ----
__device__ float g_q[(size_t)BATCH*NHEAD*SEQ*DHEAD];
__device__ float g_k[(size_t)BATCH*NHEAD*SEQ*DHEAD];
__device__ float g_v[(size_t)BATCH*NHEAD*SEQ*DHEAD];
__device__ float g_ctx[(size_t)MROWS*HIDDIM];
__device__ float g_t1[(size_t)MROWS*HIDDIM];
__device__ float g_attn[(size_t)MROWS*HIDDIM];
__device__ float g_inter[(size_t)MROWS*INTERDIM];
__device__ float g_t2[(size_t)MROWS*HIDDIM];

// ---------------- helpers ----------------------------------------------------
__device__ __forceinline__ void mma_tf32(float* c, const unsigned* a, const unsigned* b) {
    asm("mma.sync.aligned.m16n8k8.row.col.f32.tf32.tf32.f32 "
        "{%0,%1,%2,%3}, {%4,%5,%6,%7}, {%8,%9}, {%0,%1,%2,%3};"
        : "+f"(c[0]), "+f"(c[1]), "+f"(c[2]), "+f"(c[3])
        : "r"(a[0]), "r"(a[1]), "r"(a[2]), "r"(a[3]), "r"(b[0]), "r"(b[1]));
}

__device__ __forceinline__ uint32_t smem_u32(const void* p) {
    return (uint32_t)__cvta_generic_to_shared(p);
}
__device__ __forceinline__ void cp16(uint32_t dst, const void* src, int src_bytes) {
    asm volatile("cp.async.cg.shared.global [%0], [%1], 16, %2;"
                 :: "r"(dst), "l"(src), "r"(src_bytes) : "memory");
}
#define CP_COMMIT() asm volatile("cp.async.commit_group;" ::: "memory")
#define CP_WAIT1()  asm volatile("cp.async.wait_group 1;" ::: "memory")

// ============================================================================
// TF32 tensor-core GEMM, cp.async double-buffered.
// C[M,N] = A[M,K] @ W[K,N] (+epilogue). BM=128, BN=128, BK=32, 256 threads,
// 8 warps 2x4, warp tile 64x32. Raw fp32 bits as tf32 (truncation).
// ============================================================================
#define GBM 128
#define GBN 128
#define GBK 32
#define ASTRIDE 36
#define BSTRIDE 136
#define GEMM_SMEM ((2*GBM*ASTRIDE + 2*GBK*BSTRIDE) * 4)   // 71680 bytes

enum { MODE_QKV = 0, MODE_RES = 1, MODE_GELU = 2 };

struct GemmArgs {
    const float* W[3];
    const float* bias[3];
    float*       out[3];
};

template<int MODE>
__global__ __launch_bounds__(256, 2)
void mma_gemm_kernel(const float* __restrict__ A, GemmArgs ga,
                     const float* __restrict__ Rsd, int K, int N)
{
    extern __shared__ float gsm[];
    float* As = gsm;                               // [2][GBM][ASTRIDE]
    float* Bs = gsm + 2 * GBM * ASTRIDE;           // [2][GBK][BSTRIDE]

    const int tid  = threadIdx.x;
    const int warp = tid >> 5;
    const int lane = tid & 31;
    const int wm   = warp >> 2;        // 0..1
    const int wn   = warp & 3;         // 0..3
    const int lrow = lane >> 2;
    const int lcol = lane & 3;
    const int m0   = blockIdx.x * GBM;
    const int n0   = blockIdx.y * GBN;
    const int z    = blockIdx.z;

    const float* W    = ga.W[z];
    const float* bias = ga.bias[z];
    float*       out  = ga.out[z];

    float acc[4][4][4];
#pragma unroll
    for (int i = 0; i < 4; i++)
#pragma unroll
        for (int j = 0; j < 4; j++)
#pragma unroll
            for (int r = 0; r < 4; r++) acc[i][j][r] = 0.f;

    auto stage = [&](int k0, int buf) {
        float* Ab = As + buf * GBM * ASTRIDE;
        float* Bb = Bs + buf * GBK * BSTRIDE;
#pragma unroll
        for (int p = 0; p < 4; p++) {
            const int s = tid + p * 256;
            const int r = s >> 3, c = (s & 7) * 4;
            const int m = m0 + r;
            cp16(smem_u32(Ab + r * ASTRIDE + c),
                 A + (size_t)m * K + k0 + c, (m < MROWS) ? 16 : 0);
        }
#pragma unroll
        for (int p = 0; p < 4; p++) {
            const int s = tid + p * 256;
            const int r = s >> 5, c = (s & 31) * 4;
            cp16(smem_u32(Bb + r * BSTRIDE + c),
                 W + (size_t)(k0 + r) * N + n0 + c, 16);
        }
    };

    const int nkt = K / GBK;           // >= 24 always
    stage(0, 0);   CP_COMMIT();
    stage(GBK, 1); CP_COMMIT();

    for (int kt = 0; kt < nkt; kt++) {
        CP_WAIT1();
        __syncthreads();
        const int buf = kt & 1;
        const float* Ab = As + buf * GBM * ASTRIDE;
        const float* Bb = Bs + buf * GBK * BSTRIDE;

#pragma unroll
        for (int kk = 0; kk < GBK; kk += 8) {
            unsigned a[4][4], b[4][2];
#pragma unroll
            for (int i = 0; i < 4; i++) {
                const int r = wm * 64 + i * 16 + lrow;
                a[i][0] = __float_as_uint(Ab[ r      * ASTRIDE + kk + lcol    ]);
                a[i][1] = __float_as_uint(Ab[(r + 8) * ASTRIDE + kk + lcol    ]);
                a[i][2] = __float_as_uint(Ab[ r      * ASTRIDE + kk + lcol + 4]);
                a[i][3] = __float_as_uint(Ab[(r + 8) * ASTRIDE + kk + lcol + 4]);
            }
#pragma unroll
            for (int j = 0; j < 4; j++) {
                const int c = wn * 32 + j * 8 + lrow;
                b[j][0] = __float_as_uint(Bb[(kk + lcol    ) * BSTRIDE + c]);
                b[j][1] = __float_as_uint(Bb[(kk + lcol + 4) * BSTRIDE + c]);
            }
#pragma unroll
            for (int i = 0; i < 4; i++)
#pragma unroll
                for (int j = 0; j < 4; j++)
                    mma_tf32(acc[i][j], a[i], b[j]);
        }

        __syncthreads();
        if (kt + 2 < nkt) stage((kt + 2) * GBK, buf);
        CP_COMMIT();
    }

    // ---- epilogue ----
#pragma unroll
    for (int i = 0; i < 4; i++) {
#pragma unroll
        for (int rr = 0; rr < 2; rr++) {
            const int m = m0 + wm * 64 + i * 16 + lrow + rr * 8;
            if (m >= MROWS) continue;
#pragma unroll
            for (int j = 0; j < 4; j++) {
                const int nloc = wn * 32 + j * 8 + lcol * 2;
                const int n = n0 + nloc;
                const float2 b2 = *reinterpret_cast<const float2*>(bias + n);
                float x0 = acc[i][j][rr * 2 + 0] + b2.x;
                float x1 = acc[i][j][rr * 2 + 1] + b2.y;

                if (MODE == MODE_QKV) {
                    const int h = n >> 6;       // DHEAD = 64
                    const int d = n & 63;
                    const int bb = m / SEQ, srow = m % SEQ;
                    *reinterpret_cast<float2*>(
                        out + (((size_t)bb * NHEAD + h) * SEQ + srow) * DHEAD + d) =
                        make_float2(x0, x1);
                } else if (MODE == MODE_RES) {
                    const float2 r2 = *reinterpret_cast<const float2*>(Rsd + (size_t)m * N + n);
                    *reinterpret_cast<float2*>(out + (size_t)m * N + n) =
                        make_float2(x0 + r2.x, x1 + r2.y);
                } else {
                    float2 o;
                    o.x = 0.5f * x0 * (1.f + erff(x0 * 0.70710678118654752f));
                    o.y = 0.5f * x1 * (1.f + erff(x1 * 0.70710678118654752f));
                    *reinterpret_cast<float2*>(out + (size_t)m * N + n) = o;
                }
            }
        }
    }
}

// ============================================================================
// Flash attention: tf32 mma, QT=128, KT=64, 8 warps each owning 16 q-rows.
// Q fragments register-resident; K/V double-buffered via cp.async.
// ============================================================================
#define AQT 128
#define AKT 64
#define KPAD 68
#define VPAD 72
#define PPAD 68
#define FLASH_SMEM ((2*AKT*KPAD + 2*AKT*VPAD + AQT*PPAD) * 4)   // 106496

__global__ __launch_bounds__(256, 2)
void flash_attn_kernel(const float* __restrict__ Q, const float* __restrict__ Kg,
                       const float* __restrict__ Vg, const float* __restrict__ amask,
                       float* __restrict__ ctx)
{
    extern __shared__ float sm[];
    float* sK = sm;                        // [2][64][KPAD]
    float* sV = sK + 2 * AKT * KPAD;       // [2][64][VPAD]
    float* sP = sV + 2 * AKT * VPAD;       // [128][PPAD]  P staging (per-warp rows)

    const int tid  = threadIdx.x;
    const int warp = tid >> 5;
    const int lane = tid & 31;
    const int g    = lane >> 2;
    const int t4   = lane & 3;
    const int qb   = warp * 16;
    const int q0   = blockIdx.x * AQT;
    const int h    = blockIdx.y;
    const int b    = blockIdx.z;
    const size_t base = ((size_t)b * NHEAD + h) * SEQ * DHEAD;

    // ---- stage Q once (raw fp32) through sP area, then lift frags to regs ----
#pragma unroll
    for (int p = 0; p < 8; p++) {
        const int row = (tid >> 4) + p * 16;
        const int col = (tid & 15) * 4;
        float4 v = make_float4(0.f, 0.f, 0.f, 0.f);
        if (q0 + row < SEQ)
            v = *reinterpret_cast<const float4*>(Q + base + (size_t)(q0 + row) * DHEAD + col);
        *reinterpret_cast<float4*>(&sP[row * PPAD + col]) = v;
    }
    __syncthreads();

    unsigned qf[8][4];
#pragma unroll
    for (int kk = 0; kk < 8; kk++) {
        const float* qr = &sP[(qb + g) * PPAD + kk * 8 + t4];
        qf[kk][0] = __float_as_uint(qr[0]);
        qf[kk][1] = __float_as_uint(qr[8 * PPAD]);
        qf[kk][2] = __float_as_uint(qr[4]);
        qf[kk][3] = __float_as_uint(qr[8 * PPAD + 4]);
    }
    // sP is reused for P below; each warp only touches its own 16 rows, and the
    // first loop-top __syncthreads orders these reads against the first P store.

    float m_run[2] = {-1e30f, -1e30f};
    float l_run[2] = {0.f, 0.f};
    float o[8][4];
#pragma unroll
    for (int j = 0; j < 8; j++)
#pragma unroll
        for (int r = 0; r < 4; r++) o[j][r] = 0.f;

    const bool lead_warp = (q0 == 0 && warp == 0);
    const int nkt = (SEQ + AKT - 1) / AKT;   // 19

    auto stageKV = [&](int kt, int buf) {
        const int k0 = kt * AKT;
        float* Kb = sK + buf * AKT * KPAD;
        float* Vb = sV + buf * AKT * VPAD;
#pragma unroll
        for (int p = 0; p < 4; p++) {
            const int s = tid + p * 256;
            const int row = s >> 4, c = (s & 15) * 4;
            const int sz = (k0 + row < SEQ) ? 16 : 0;
            const size_t off = base + (size_t)(k0 + row) * DHEAD + c;
            cp16(smem_u32(Kb + row * KPAD + c), Kg + off, sz);
            cp16(smem_u32(Vb + row * VPAD + c), Vg + off, sz);
        }
    };

    stageKV(0, 0); CP_COMMIT();
    stageKV(1, 1); CP_COMMIT();     // nkt = 19 > 1 always

    for (int kt = 0; kt < nkt; kt++) {
        const int k0 = kt * AKT;
        const int buf = kt & 1;
        CP_WAIT1();
        __syncthreads();
        const float* Kb = sK + buf * AKT * KPAD;
        const float* Vb = sV + buf * AKT * VPAD;

        // ---- S = Q @ K^T ----
        float sc[8][4];
#pragma unroll
        for (int j = 0; j < 8; j++)
#pragma unroll
            for (int r = 0; r < 4; r++) sc[j][r] = 0.f;

#pragma unroll
        for (int kk = 0; kk < 8; kk++) {
#pragma unroll
            for (int j = 0; j < 8; j++) {
                unsigned bb[2];
                const float* kr = &Kb[(j * 8 + g) * KPAD + kk * 8 + t4];
                bb[0] = __float_as_uint(kr[0]);
                bb[1] = __float_as_uint(kr[4]);
                mma_tf32(sc[j], qf[kk], bb);
            }
        }

        // ---- scale (1/sqrt(64)=0.125) + masks ----
#pragma unroll
        for (int j = 0; j < 8; j++) {
#pragma unroll
            for (int e = 0; e < 2; e++) {
                const int cg = k0 + j * 8 + 2 * t4 + e;
                const float am = (cg < SEQ) ? __ldg(amask + (size_t)b * SEQ + cg) : 0.f;
#pragma unroll
                for (int rr = 0; rr < 2; rr++) {
                    float val = fmaf(sc[j][rr * 2 + e], 0.125f, am);
                    if (cg >= SEQ) val = -1e30f;
                    if (lead_warp) {
                        const int qg = qb + g + rr * 8;   // q0 == 0 here
                        if (qg == 0) {
                            if (cg >= 1 && cg < 1 + NLEAD) val -= 99999.f;
                        } else if (qg >= 1 && qg <= NLEAD) {
                            const int start = NLEAD + 1 + 100 * (qg - 1);
                            if (!(cg >= start && cg < start + 100)) val -= 99999.f;
                        }
                    }
                    sc[j][rr * 2 + e] = val;
                }
            }
        }

        // ---- online softmax (rows live in 4-lane groups) ----
#pragma unroll
        for (int rr = 0; rr < 2; rr++) {
            float mt = -1e30f;
#pragma unroll
            for (int j = 0; j < 8; j++)
                mt = fmaxf(mt, fmaxf(sc[j][rr * 2], sc[j][rr * 2 + 1]));
            mt = fmaxf(mt, __shfl_xor_sync(0xffffffffu, mt, 1));
            mt = fmaxf(mt, __shfl_xor_sync(0xffffffffu, mt, 2));
            const float mnew = fmaxf(m_run[rr], mt);
            const float fac = __expf(m_run[rr] - mnew);
            m_run[rr] = mnew;
            float ls = 0.f;
#pragma unroll
            for (int j = 0; j < 8; j++) {
                const float p0 = __expf(sc[j][rr * 2    ] - mnew);
                const float p1 = __expf(sc[j][rr * 2 + 1] - mnew);
                sc[j][rr * 2    ] = p0;
                sc[j][rr * 2 + 1] = p1;
                ls += p0 + p1;
            }
            ls += __shfl_xor_sync(0xffffffffu, ls, 1);
            ls += __shfl_xor_sync(0xffffffffu, ls, 2);
            l_run[rr] = l_run[rr] * fac + ls;
#pragma unroll
            for (int j = 0; j < 8; j++) {
                o[j][rr * 2    ] *= fac;
                o[j][rr * 2 + 1] *= fac;
            }
        }

        // ---- store P (raw fp32) to this warp's private sP rows ----
#pragma unroll
        for (int rr = 0; rr < 2; rr++)
#pragma unroll
            for (int j = 0; j < 8; j++)
                *reinterpret_cast<float2*>(
                    &sP[(qb + g + rr * 8) * PPAD + j * 8 + 2 * t4]) =
                    make_float2(sc[j][rr * 2], sc[j][rr * 2 + 1]);
        __syncwarp();

        // ---- O += P @ V ----
#pragma unroll
        for (int kk = 0; kk < 8; kk++) {
            unsigned a[4];
            const float* pr = &sP[(qb + g) * PPAD + kk * 8 + t4];
            a[0] = __float_as_uint(pr[0]);
            a[1] = __float_as_uint(pr[8 * PPAD]);
            a[2] = __float_as_uint(pr[4]);
            a[3] = __float_as_uint(pr[8 * PPAD + 4]);
#pragma unroll
            for (int j = 0; j < 8; j++) {
                unsigned bb[2];
                const float* vr = &Vb[(kk * 8 + t4) * VPAD + j * 8 + g];
                bb[0] = __float_as_uint(vr[0]);
                bb[1] = __float_as_uint(vr[4 * VPAD]);
                mma_tf32(o[j], a, bb);
            }
        }

        __syncthreads();                   // all warps done with this buf
        if (kt + 2 < nkt) stageKV(kt + 2, buf);
        CP_COMMIT();
    }

    // ---- epilogue: normalize and write ctx [B,S,HID] ----
#pragma unroll
    for (int rr = 0; rr < 2; rr++) {
        const int qg = q0 + qb + g + rr * 8;
        if (qg < SEQ) {
            const float inv = 1.f / l_run[rr];
#pragma unroll
            for (int j = 0; j < 8; j++) {
                float2 ov;
                ov.x = o[j][rr * 2    ] * inv;
                ov.y = o[j][rr * 2 + 1] * inv;
                *reinterpret_cast<float2*>(
                    ctx + ((size_t)b * SEQ + qg) * HIDDIM + h * DHEAD + j * 8 + 2 * t4) = ov;
            }
        }
    }
}

// ---------------- LayerNorm (one block per row, HID=768, 256 threads) -------
__global__ __launch_bounds__(256)
void layernorm_kernel(const float* __restrict__ x, const float* __restrict__ g,
                      const float* __restrict__ bb, float* __restrict__ y)
{
    __shared__ float red[8];
    __shared__ float sMean, sRstd;
    const int row = blockIdx.x;
    const int tid = threadIdx.x;
    const float* xr = x + (size_t)row * HIDDIM;

    float v[3];
    float sum = 0.f;
#pragma unroll
    for (int i = 0; i < 3; i++) { v[i] = xr[tid + i * 256]; sum += v[i]; }

#pragma unroll
    for (int o = 16; o > 0; o >>= 1) sum += __shfl_down_sync(0xffffffffu, sum, o);
    if ((tid & 31) == 0) red[tid >> 5] = sum;
    __syncthreads();
    if (tid < 32) {
        float t = (tid < 8) ? red[tid] : 0.f;
#pragma unroll
        for (int o = 4; o > 0; o >>= 1) t += __shfl_down_sync(0xffffffffu, t, o);
        if (tid == 0) sMean = t * (1.f / HIDDIM);
    }
    __syncthreads();
    const float mean = sMean;

    float sq = 0.f;
#pragma unroll
    for (int i = 0; i < 3; i++) { float d = v[i] - mean; sq += d * d; }
#pragma unroll
    for (int o = 16; o > 0; o >>= 1) sq += __shfl_down_sync(0xffffffffu, sq, o);
    __syncthreads();
    if ((tid & 31) == 0) red[tid >> 5] = sq;
    __syncthreads();
    if (tid < 32) {
        float t = (tid < 8) ? red[tid] : 0.f;
#pragma unroll
        for (int o = 4; o > 0; o >>= 1) t += __shfl_down_sync(0xffffffffu, t, o);
        if (tid == 0) sRstd = rsqrtf(t * (1.f / HIDDIM) + 1e-12f);
    }
    __syncthreads();
    const float rstd = sRstd;

#pragma unroll
    for (int i = 0; i < 3; i++) {
        int c = tid + i * 256;
        y[(size_t)row * HIDDIM + c] = g[c] * (v[i] - mean) * rstd + bb[c];
    }
}

// ---------------- launch ----------------------------------------------------
extern "C" void kernel_launch(void* const* d_in, const int* in_sizes, int n_in,
                              void* d_out, int out_size)
{
    const float* hs    = (const float*)d_in[0];
    const float* amask = (const float*)d_in[1];
    const float* Wq = (const float*)d_in[2];  const float* bq = (const float*)d_in[3];
    const float* Wk = (const float*)d_in[4];  const float* bk = (const float*)d_in[5];
    const float* Wv = (const float*)d_in[6];  const float* bv = (const float*)d_in[7];
    const float* Wo = (const float*)d_in[8];  const float* bo = (const float*)d_in[9];
    const float* g1 = (const float*)d_in[10]; const float* b1 = (const float*)d_in[11];
    const float* Wi = (const float*)d_in[12]; const float* bi = (const float*)d_in[13];
    const float* Wd = (const float*)d_in[14]; const float* bd = (const float*)d_in[15];
    const float* g2 = (const float*)d_in[16]; const float* b2 = (const float*)d_in[17];
    float* out = (float*)d_out;

    float *q, *k, *v, *ctx, *t1, *attn, *inter, *t2;
    cudaGetSymbolAddress((void**)&q,     g_q);
    cudaGetSymbolAddress((void**)&k,     g_k);
    cudaGetSymbolAddress((void**)&v,     g_v);
    cudaGetSymbolAddress((void**)&ctx,   g_ctx);
    cudaGetSymbolAddress((void**)&t1,    g_t1);
    cudaGetSymbolAddress((void**)&attn,  g_attn);
    cudaGetSymbolAddress((void**)&inter, g_inter);
    cudaGetSymbolAddress((void**)&t2,    g_t2);

    cudaFuncSetAttribute(flash_attn_kernel,
                         cudaFuncAttributeMaxDynamicSharedMemorySize, FLASH_SMEM);
    cudaFuncSetAttribute(mma_gemm_kernel<MODE_QKV>,
                         cudaFuncAttributeMaxDynamicSharedMemorySize, GEMM_SMEM);
    cudaFuncSetAttribute(mma_gemm_kernel<MODE_RES>,
                         cudaFuncAttributeMaxDynamicSharedMemorySize, GEMM_SMEM);
    cudaFuncSetAttribute(mma_gemm_kernel<MODE_GELU>,
                         cudaFuncAttributeMaxDynamicSharedMemorySize, GEMM_SMEM);

    const int mblk = (MROWS + GBM - 1) / GBM;                    // 76

    // QKV fused in one launch: grid.z selects {q,k,v}
    {
        GemmArgs ga;
        ga.W[0] = Wq; ga.W[1] = Wk; ga.W[2] = Wv;
        ga.bias[0] = bq; ga.bias[1] = bk; ga.bias[2] = bv;
        ga.out[0] = q; ga.out[1] = k; ga.out[2] = v;
        dim3 grid(mblk, HIDDIM / GBN, 3);                        // 76 x 6 x 3
        mma_gemm_kernel<MODE_QKV><<<grid, 256, GEMM_SMEM>>>(hs, ga, nullptr, HIDDIM, HIDDIM);
    }

    // attention -> ctx [B,S,HID]
    dim3 gAtt((SEQ + AQT - 1) / AQT, NHEAD, BATCH);              // 10 x 12 x 8
    flash_attn_kernel<<<gAtt, 256, FLASH_SMEM>>>(q, k, v, amask, ctx);

    // O-proj + residual, then LN1
    {
        GemmArgs ga = {};
        ga.W[0] = Wo; ga.bias[0] = bo; ga.out[0] = t1;
        dim3 grid(mblk, HIDDIM / GBN, 1);
        mma_gemm_kernel<MODE_RES><<<grid, 256, GEMM_SMEM>>>(ctx, ga, hs, HIDDIM, HIDDIM);
    }
    layernorm_kernel<<<MROWS, 256>>>(t1, g1, b1, attn);

    // FFN
    {
        GemmArgs ga = {};
        ga.W[0] = Wi; ga.bias[0] = bi; ga.out[0] = inter;
        dim3 grid(mblk, INTERDIM / GBN, 1);
        mma_gemm_kernel<MODE_GELU><<<grid, 256, GEMM_SMEM>>>(attn, ga, nullptr, HIDDIM, INTERDIM);
    }
    {
        GemmArgs ga = {};
        ga.W[0] = Wd; ga.bias[0] = bd; ga.out[0] = t2;
        dim3 grid(mblk, HIDDIM / GBN, 1);
        mma_gemm_kernel<MODE_RES><<<grid, 256, GEMM_SMEM>>>(inter, ga, attn, INTERDIM, HIDDIM);
    }
    layernorm_kernel<<<MROWS, 256>>>(t2, g2, b2, out);
}